// round 2
// baseline (speedup 1.0000x reference)
#include <cuda_runtime.h>
#include <math.h>

#define BATCH 8
#define SEQ   2048
#define DIM   128
#define HDIM  128
#define MASK_VALUE -1e30f

// Scratch for projected q and k (8 MB each) — device globals, no allocation.
__device__ float g_q[BATCH * SEQ * HDIM];
__device__ float g_k[BATCH * SEQ * HDIM];

// ---------------------------------------------------------------------------
// Projection GEMM: Out[m, h] = sum_d X[m, d] * W[d, h]
// M = BATCH*SEQ = 16384, N = 128, K = 128.
// Block tile 128(M) x 128(N), 256 threads, 8x8 micro-tile per thread.
// blockIdx.y selects (query,Wq)->g_q vs (key,Wk)->g_k.
// ---------------------------------------------------------------------------
__global__ __launch_bounds__(256) void proj_kernel(const float* __restrict__ Xq,
                                                   const float* __restrict__ Xk,
                                                   const float* __restrict__ Wq,
                                                   const float* __restrict__ Wk) {
    __shared__ float As[8][128];   // [k][m]
    __shared__ float Bs[8][128];   // [k][n]

    const int tid = threadIdx.x;
    const int tx  = tid & 15;      // column group
    const int ty  = tid >> 4;      // row group
    const int m0  = blockIdx.x * 128;

    const float* __restrict__ X = (blockIdx.y == 0) ? Xq : Xk;
    const float* __restrict__ W = (blockIdx.y == 0) ? Wq : Wk;
    float* __restrict__ Out     = (blockIdx.y == 0) ? g_q : g_k;

    float acc[8][8];
#pragma unroll
    for (int i = 0; i < 8; i++)
#pragma unroll
        for (int j = 0; j < 8; j++) acc[i][j] = 0.f;

    for (int k0 = 0; k0 < DIM; k0 += 8) {
        // Load A tile (128 rows x 8 k), stored transposed As[k][m].
        {
            const int row = tid >> 1;
            const int u   = (tid & 1) * 4;
            float4 x = *(const float4*)&X[(size_t)(m0 + row) * DIM + k0 + u];
            As[u + 0][row] = x.x;
            As[u + 1][row] = x.y;
            As[u + 2][row] = x.z;
            As[u + 3][row] = x.w;
        }
        // Load B tile (8 k x 128 n).
        {
            const int kk = tid >> 5;
            const int n0 = (tid & 31) * 4;
            *(float4*)&Bs[kk][n0] = *(const float4*)&W[(size_t)(k0 + kk) * HDIM + n0];
        }
        __syncthreads();

#pragma unroll
        for (int k = 0; k < 8; k++) {
            float ra[8], rb[8];
            *(float4*)&ra[0] = *(float4*)&As[k][ty * 8];
            *(float4*)&ra[4] = *(float4*)&As[k][ty * 8 + 4];
#pragma unroll
            for (int nn = 0; nn < 8; nn++) rb[nn] = Bs[k][tx + 16 * nn];
#pragma unroll
            for (int rr = 0; rr < 8; rr++)
#pragma unroll
                for (int nn = 0; nn < 8; nn++)
                    acc[rr][nn] = fmaf(ra[rr], rb[nn], acc[rr][nn]);
        }
        __syncthreads();
    }

#pragma unroll
    for (int rr = 0; rr < 8; rr++)
#pragma unroll
        for (int nn = 0; nn < 8; nn++)
            Out[(size_t)(m0 + ty * 8 + rr) * HDIM + tx + 16 * nn] = acc[rr][nn];
}

// ---------------------------------------------------------------------------
// Fused masked-softmax attention (flash style), fp32.
// Block: 64 queries x full head (128). 256 threads = 16x16.
// Thread owns S rows ty*4..+4, S cols {tx + 16*jj}, O cols {tx + 16*dd}.
// Smem tiles padded/transposed so every inner-loop LDS is <=2-way conflicted.
// ---------------------------------------------------------------------------
#define BM 64
#define BN 64
#define QSTR 132   // Qs row stride (floats)
#define KSTR 132   // Ks row stride
#define VSTR 68    // VsT row stride (transposed: [d][j])
#define PSTR 68    // Ps row stride

// floats: Qs 64*132 + Ks 64*132 + VsT 128*68 + Ps 64*68 + ms 64
#define ATTN_SMEM_FLOATS (64 * QSTR + 64 * KSTR + 128 * VSTR + 64 * PSTR + 64)
#define ATTN_SMEM_BYTES  (ATTN_SMEM_FLOATS * 4)

extern __shared__ float smem_attn[];

__global__ __launch_bounds__(256) void attn_kernel(const float* __restrict__ Vg,
                                                   const float* __restrict__ maskg,
                                                   float* __restrict__ Outg) {
    float* Qs  = smem_attn;
    float* Ks  = Qs + 64 * QSTR;
    float* VsT = Ks + 64 * KSTR;
    float* Ps  = VsT + 128 * VSTR;
    float* ms  = Ps + 64 * PSTR;

    const int tid = threadIdx.x;
    const int tx  = tid & 15;
    const int ty  = tid >> 4;
    const int b   = blockIdx.y;
    const int q0  = blockIdx.x * BM;

    const float* __restrict__ qg     = g_q + ((size_t)b * SEQ + q0) * HDIM;
    const float* __restrict__ kgbase = g_k + (size_t)b * SEQ * HDIM;
    const float* __restrict__ vgbase = Vg + (size_t)b * SEQ * DIM;
    const float* __restrict__ mbase  = maskg + (size_t)b * SEQ;

    // Load Q tile (64 x 128).
#pragma unroll
    for (int i = tid; i < 64 * 32; i += 256) {
        const int row = i >> 5;
        const int c4  = (i & 31) * 4;
        *(float4*)&Qs[row * QSTR + c4] = *(const float4*)&qg[(size_t)row * HDIM + c4];
    }

    float m_cur[4], l_cur[4], acc[4][8];
#pragma unroll
    for (int ii = 0; ii < 4; ii++) {
        m_cur[ii] = -INFINITY;
        l_cur[ii] = 0.f;
#pragma unroll
        for (int dd = 0; dd < 8; dd++) acc[ii][dd] = 0.f;
    }

    for (int k0 = 0; k0 < SEQ; k0 += BN) {
        __syncthreads();  // previous PV must be done before overwriting Ks/VsT

        // Load K tile (row-major, padded).
#pragma unroll
        for (int i = tid; i < 64 * 32; i += 256) {
            const int row = i >> 5;
            const int c4  = (i & 31) * 4;
            *(float4*)&Ks[row * KSTR + c4] =
                *(const float4*)&kgbase[(size_t)(k0 + row) * HDIM + c4];
        }
        // Load V tile transposed: VsT[d][j].
#pragma unroll
        for (int i = tid; i < 64 * 32; i += 256) {
            const int row = i >> 5;
            const int c4  = (i & 31) * 4;
            float4 v = *(const float4*)&vgbase[(size_t)(k0 + row) * DIM + c4];
            VsT[(c4 + 0) * VSTR + row] = v.x;
            VsT[(c4 + 1) * VSTR + row] = v.y;
            VsT[(c4 + 2) * VSTR + row] = v.z;
            VsT[(c4 + 3) * VSTR + row] = v.w;
        }
        if (tid < BN) ms[tid] = mbase[k0 + tid];
        __syncthreads();

        // ---- S = Q @ K^T (64x64), thread computes 4x4 at cols tx+16*jj ----
        float s[4][4];
#pragma unroll
        for (int ii = 0; ii < 4; ii++)
#pragma unroll
            for (int jj = 0; jj < 4; jj++) s[ii][jj] = 0.f;

#pragma unroll 4
        for (int d0 = 0; d0 < HDIM; d0 += 4) {
            float4 rq[4], rk[4];
#pragma unroll
            for (int ii = 0; ii < 4; ii++)
                rq[ii] = *(float4*)&Qs[(ty * 4 + ii) * QSTR + d0];
#pragma unroll
            for (int jj = 0; jj < 4; jj++)
                rk[jj] = *(float4*)&Ks[(tx + 16 * jj) * KSTR + d0];
#pragma unroll
            for (int ii = 0; ii < 4; ii++)
#pragma unroll
                for (int jj = 0; jj < 4; jj++) {
                    s[ii][jj] = fmaf(rq[ii].x, rk[jj].x, s[ii][jj]);
                    s[ii][jj] = fmaf(rq[ii].y, rk[jj].y, s[ii][jj]);
                    s[ii][jj] = fmaf(rq[ii].z, rk[jj].z, s[ii][jj]);
                    s[ii][jj] = fmaf(rq[ii].w, rk[jj].w, s[ii][jj]);
                }
        }

        // ---- mask + online softmax ----
        float mv[4];
#pragma unroll
        for (int jj = 0; jj < 4; jj++) mv[jj] = ms[tx + 16 * jj];
#pragma unroll
        for (int ii = 0; ii < 4; ii++)
#pragma unroll
            for (int jj = 0; jj < 4; jj++)
                s[ii][jj] = mv[jj] * s[ii][jj] + (1.f - mv[jj]) * MASK_VALUE;

#pragma unroll
        for (int ii = 0; ii < 4; ii++) {
            float mx = s[ii][0];
#pragma unroll
            for (int jj = 1; jj < 4; jj++) mx = fmaxf(mx, s[ii][jj]);
#pragma unroll
            for (int off = 8; off >= 1; off >>= 1)
                mx = fmaxf(mx, __shfl_xor_sync(0xffffffffu, mx, off, 16));

            const float mnew  = fmaxf(m_cur[ii], mx);
            const float alpha = __expf(m_cur[ii] - mnew);  // exp(-inf)=0 first tile
            float rs = 0.f;
#pragma unroll
            for (int jj = 0; jj < 4; jj++) {
                const float p = __expf(s[ii][jj] - mnew);
                s[ii][jj] = p;
                rs += p;
            }
#pragma unroll
            for (int off = 8; off >= 1; off >>= 1)
                rs += __shfl_xor_sync(0xffffffffu, rs, off, 16);

            l_cur[ii] = l_cur[ii] * alpha + rs;
            m_cur[ii] = mnew;
#pragma unroll
            for (int dd = 0; dd < 8; dd++) acc[ii][dd] *= alpha;
#pragma unroll
            for (int jj = 0; jj < 4; jj++)
                Ps[(ty * 4 + ii) * PSTR + tx + 16 * jj] = s[ii][jj];
        }
        __syncthreads();

        // ---- O += P @ V (P from smem, V transposed) ----
#pragma unroll 2
        for (int j0 = 0; j0 < BN; j0 += 4) {
            float4 rp[4], rv[8];
#pragma unroll
            for (int ii = 0; ii < 4; ii++)
                rp[ii] = *(float4*)&Ps[(ty * 4 + ii) * PSTR + j0];
#pragma unroll
            for (int dd = 0; dd < 8; dd++)
                rv[dd] = *(float4*)&VsT[(tx + 16 * dd) * VSTR + j0];
#pragma unroll
            for (int ii = 0; ii < 4; ii++)
#pragma unroll
                for (int dd = 0; dd < 8; dd++) {
                    acc[ii][dd] = fmaf(rp[ii].x, rv[dd].x, acc[ii][dd]);
                    acc[ii][dd] = fmaf(rp[ii].y, rv[dd].y, acc[ii][dd]);
                    acc[ii][dd] = fmaf(rp[ii].z, rv[dd].z, acc[ii][dd]);
                    acc[ii][dd] = fmaf(rp[ii].w, rv[dd].w, acc[ii][dd]);
                }
        }
    }

    // ---- epilogue: normalize and write out ----
#pragma unroll
    for (int ii = 0; ii < 4; ii++) {
        const float inv = (l_cur[ii] > 0.f) ? (1.f / l_cur[ii]) : 0.f;
        const size_t row = (size_t)b * SEQ + q0 + ty * 4 + ii;
#pragma unroll
        for (int dd = 0; dd < 8; dd++)
            Outg[row * DIM + tx + 16 * dd] = acc[ii][dd] * inv;
    }
}

// ---------------------------------------------------------------------------
extern "C" void kernel_launch(void* const* d_in, const int* in_sizes, int n_in,
                              void* d_out, int out_size) {
    (void)in_sizes; (void)n_in; (void)out_size;
    const float* query = (const float*)d_in[0];
    const float* key   = (const float*)d_in[1];
    const float* value = (const float*)d_in[2];
    const float* mask  = (const float*)d_in[3];
    const float* Wq    = (const float*)d_in[4];
    const float* Wk    = (const float*)d_in[5];
    float* out = (float*)d_out;

    cudaFuncSetAttribute(attn_kernel, cudaFuncAttributeMaxDynamicSharedMemorySize,
                         ATTN_SMEM_BYTES);

    // Projections: q = query@Wq, k = key@Wk into device scratch.
    proj_kernel<<<dim3(BATCH * SEQ / 128, 2), 256>>>(query, key, Wq, Wk);

    // Fused masked softmax attention.
    attn_kernel<<<dim3(SEQ / BM, BATCH), 256, ATTN_SMEM_BYTES>>>(value, mask, out);
}

// round 4
// speedup vs baseline: 3.5256x; 3.5256x over previous
#include <cuda_runtime.h>
#include <cuda_bf16.h>
#include <math.h>
#include <stdint.h>

#define BATCH 8
#define SEQ   2048
#define DIM   128
#define HDIM  128
#define MASK_VALUE -1e30f

// fp32 scratch for projected q, k
__device__ float g_q[BATCH * SEQ * HDIM];
__device__ float g_k[BATCH * SEQ * HDIM];
// bf16-split K (row-major [b*SEQ][128] as packed bf16x2 words; 16 uint4 per row)
__device__ uint4 g_khi4[BATCH * SEQ * 16];
__device__ uint4 g_klo4[BATCH * SEQ * 16];
// bf16-split transposed V: VT[b][d][kv] packed pairs along kv (1024 words per (b,d))
__device__ uint4 g_vthi4[BATCH * 128 * 256];
__device__ uint4 g_vtlo4[BATCH * 128 * 256];

// ---------------- helpers ----------------
__device__ __forceinline__ void split2(float x, float y, uint32_t& hi, uint32_t& lo) {
    __nv_bfloat16 hx = __float2bfloat16(x), hy = __float2bfloat16(y);
    __nv_bfloat16 lx = __float2bfloat16(x - __bfloat162float(hx));
    __nv_bfloat16 ly = __float2bfloat16(y - __bfloat162float(hy));
    hi = ((uint32_t)__bfloat16_as_ushort(hy) << 16) | (uint32_t)__bfloat16_as_ushort(hx);
    lo = ((uint32_t)__bfloat16_as_ushort(ly) << 16) | (uint32_t)__bfloat16_as_ushort(lx);
}

__device__ __forceinline__ void mma16816(float* d, const uint32_t* a, const uint32_t* b) {
    asm volatile(
        "mma.sync.aligned.m16n8k16.row.col.f32.bf16.bf16.f32 "
        "{%0,%1,%2,%3}, {%4,%5,%6,%7}, {%8,%9}, {%0,%1,%2,%3};"
        : "+f"(d[0]), "+f"(d[1]), "+f"(d[2]), "+f"(d[3])
        : "r"(a[0]), "r"(a[1]), "r"(a[2]), "r"(a[3]), "r"(b[0]), "r"(b[1]));
}

// ---------------- projection GEMM (round-1, proven) ----------------
__global__ __launch_bounds__(256) void proj_kernel(const float* __restrict__ Xq,
                                                   const float* __restrict__ Xk,
                                                   const float* __restrict__ Wq,
                                                   const float* __restrict__ Wk) {
    __shared__ float As[8][128];
    __shared__ float Bs[8][128];
    const int tid = threadIdx.x, tx = tid & 15, ty = tid >> 4;
    const int m0 = blockIdx.x * 128;
    const float* __restrict__ X = (blockIdx.y == 0) ? Xq : Xk;
    const float* __restrict__ W = (blockIdx.y == 0) ? Wq : Wk;
    float* __restrict__ Out     = (blockIdx.y == 0) ? g_q : g_k;
    float acc[8][8];
#pragma unroll
    for (int i = 0; i < 8; i++)
#pragma unroll
        for (int j = 0; j < 8; j++) acc[i][j] = 0.f;
    for (int k0 = 0; k0 < DIM; k0 += 8) {
        {
            const int row = tid >> 1, u = (tid & 1) * 4;
            float4 x = *(const float4*)&X[(size_t)(m0 + row) * DIM + k0 + u];
            As[u][row] = x.x; As[u + 1][row] = x.y; As[u + 2][row] = x.z; As[u + 3][row] = x.w;
        }
        {
            const int kk = tid >> 5, n0 = (tid & 31) * 4;
            *(float4*)&Bs[kk][n0] = *(const float4*)&W[(size_t)(k0 + kk) * HDIM + n0];
        }
        __syncthreads();
#pragma unroll
        for (int k = 0; k < 8; k++) {
            float ra[8], rb[8];
            *(float4*)&ra[0] = *(float4*)&As[k][ty * 8];
            *(float4*)&ra[4] = *(float4*)&As[k][ty * 8 + 4];
#pragma unroll
            for (int nn = 0; nn < 8; nn++) rb[nn] = Bs[k][tx + 16 * nn];
#pragma unroll
            for (int rr = 0; rr < 8; rr++)
#pragma unroll
                for (int nn = 0; nn < 8; nn++) acc[rr][nn] = fmaf(ra[rr], rb[nn], acc[rr][nn]);
        }
        __syncthreads();
    }
#pragma unroll
    for (int rr = 0; rr < 8; rr++)
#pragma unroll
        for (int nn = 0; nn < 8; nn++)
            Out[(size_t)(m0 + ty * 8 + rr) * HDIM + tx + 16 * nn] = acc[rr][nn];
}

// ---------------- split K into bf16 hi/lo ----------------
__global__ __launch_bounds__(256) void splitk_kernel() {
    const int i = blockIdx.x * 256 + threadIdx.x;   // word index, N = B*SEQ*64
    const float2 v = ((const float2*)g_k)[i];
    uint32_t h, l;
    split2(v.x, v.y, h, l);
    ((uint32_t*)g_khi4)[i] = h;
    ((uint32_t*)g_klo4)[i] = l;
}

// ---------------- V: transpose + split -> g_vthi/g_vtlo ----------------
__global__ __launch_bounds__(256) void vprep_kernel(const float* __restrict__ Vg) {
    __shared__ float stg[64 * 132];
    const int tid = threadIdx.x;
    const int kv0 = blockIdx.x * 64;
    const int b   = blockIdx.y;
    // load V tile [64 kv][128 d]
#pragma unroll
    for (int it = 0; it < 8; it++) {
        const int u = tid + it * 256;           // 2048 float4
        const int row = u >> 5, c4 = (u & 31) * 4;
        *(float4*)&stg[row * 132 + c4] =
            *(const float4*)&Vg[(size_t)(b * SEQ + kv0 + row) * DIM + c4];
    }
    __syncthreads();
    const int d = tid & 127, half = tid >> 7;
    uint32_t* oh = (uint32_t*)g_vthi4;
    uint32_t* ol = (uint32_t*)g_vtlo4;
#pragma unroll
    for (int i = 0; i < 16; i++) {
        const int kvw = half * 16 + i;
        uint32_t h, l;
        split2(stg[(2 * kvw) * 132 + d], stg[(2 * kvw + 1) * 132 + d], h, l);
        const int dst = (b * 128 + d) * 1024 + (kv0 >> 1) + kvw;
        oh[dst] = h;
        ol[dst] = l;
    }
}

// ---------------- fused flash attention on HMMA ----------------
// smem byte offsets (word strides: Q 68, K 68, VT 36 -> conflict-free frags)
#define SQH 0
#define SQL 34816
#define SKH 69632
#define SKL 87040
#define SVH 104448
#define SVL 122880
#define SMS 141312
#define SM_TOTAL 141568

extern __shared__ __align__(16) char smx[];

__global__ void __launch_bounds__(256, 1)
attn_hmma(const float* __restrict__ Vg, const float* __restrict__ maskg,
          float* __restrict__ Outg) {
    const int tid = threadIdx.x, lane = tid & 31, w = tid >> 5;
    const int g = lane >> 2, t = lane & 3;
    const int b = blockIdx.y, q0 = blockIdx.x * 128;

    uint32_t* Qh = (uint32_t*)(smx + SQH);
    uint32_t* Ql = (uint32_t*)(smx + SQL);
    uint32_t* Kh = (uint32_t*)(smx + SKH);
    uint32_t* Kl = (uint32_t*)(smx + SKL);
    uint32_t* Vh = (uint32_t*)(smx + SVH);
    uint32_t* Vl = (uint32_t*)(smx + SVL);
    float*    ms = (float*)(smx + SMS);

    // ---- load + split Q tile (128 x 128) ----
    const float2* q2 = (const float2*)(g_q + ((size_t)b * SEQ + q0) * HDIM);
#pragma unroll
    for (int it = 0; it < 32; it++) {
        const int i = tid + it * 256;          // 8192 float2
        const int row = i >> 6, wd = i & 63;
        const float2 v = q2[row * 64 + wd];
        uint32_t h, l;
        split2(v.x, v.y, h, l);
        Qh[row * 68 + wd] = h;
        Ql[row * 68 + wd] = l;
    }

    const float* mb = maskg + (size_t)b * SEQ;
    const int rg = w * 16 + g;                  // warp-local row g (global q row = q0+rg)
    const uint32_t* qhp = Qh + rg * 68;
    const uint32_t* qlp = Ql + rg * 68;

    float oacc[16][4];
#pragma unroll
    for (int n = 0; n < 16; n++)
#pragma unroll
        for (int i = 0; i < 4; i++) oacc[n][i] = 0.f;
    float m0 = -INFINITY, m1 = -INFINITY, l0 = 0.f, l1 = 0.f;

    for (int it = 0; it < SEQ / 64; it++) {
        const int kv0 = it * 64;
        __syncthreads();  // previous iter's smem reads complete

        // ---- copy K tile (64 x 128, hi+lo) ----
#pragma unroll
        for (int u4 = 0; u4 < 4; u4++) {
            const int u = tid + u4 * 256;       // 1024 uint4
            const int row = u >> 4, c = u & 15;
            const int src = ((b * SEQ + kv0 + row) << 4) + c;
            *(uint4*)(smx + SKH + row * 272 + c * 16) = g_khi4[src];
            *(uint4*)(smx + SKL + row * 272 + c * 16) = g_klo4[src];
        }
        // ---- copy VT tile (128 d x 64 kv, hi+lo) ----
#pragma unroll
        for (int u4 = 0; u4 < 4; u4++) {
            const int u = tid + u4 * 256;       // 1024 uint4
            const int row = u >> 3, c = u & 7;
            const int src = (b * 128 + row) * 256 + it * 8 + c;
            *(uint4*)(smx + SVH + row * 144 + c * 16) = g_vthi4[src];
            *(uint4*)(smx + SVL + row * 144 + c * 16) = g_vtlo4[src];
        }
        if (tid < 64) ms[tid] = mb[kv0 + tid];
        __syncthreads();

        // ---- S = Q K^T (16 x 64 per warp), 3-product bf16 emulation ----
        float sacc[8][4];
#pragma unroll
        for (int j = 0; j < 8; j++)
#pragma unroll
            for (int i = 0; i < 4; i++) sacc[j][i] = 0.f;

#pragma unroll
        for (int k = 0; k < 8; k++) {
            const int k8 = k * 8;
            uint32_t ah[4], al[4];
            ah[0] = qhp[k8 + t];        ah[1] = qhp[544 + k8 + t];
            ah[2] = qhp[k8 + 4 + t];    ah[3] = qhp[544 + k8 + 4 + t];
            al[0] = qlp[k8 + t];        al[1] = qlp[544 + k8 + t];
            al[2] = qlp[k8 + 4 + t];    al[3] = qlp[544 + k8 + 4 + t];
#pragma unroll
            for (int j = 0; j < 8; j++) {
                const int base = (j * 8 + g) * 68 + k8 + t;
                uint32_t bh[2], bl[2];
                bh[0] = Kh[base]; bh[1] = Kh[base + 4];
                bl[0] = Kl[base]; bl[1] = Kl[base + 4];
                mma16816(sacc[j], ah, bh);
                mma16816(sacc[j], ah, bl);
                mma16816(sacc[j], al, bh);
            }
        }

        // ---- mask + online softmax (rows g and g+8 per lane quad) ----
        float rmax0 = -INFINITY, rmax1 = -INFINITY;
#pragma unroll
        for (int j = 0; j < 8; j++) {
            const float mva = ms[j * 8 + t * 2], mvb = ms[j * 8 + t * 2 + 1];
            sacc[j][0] = mva * sacc[j][0] + (1.f - mva) * MASK_VALUE;
            sacc[j][1] = mvb * sacc[j][1] + (1.f - mvb) * MASK_VALUE;
            sacc[j][2] = mva * sacc[j][2] + (1.f - mva) * MASK_VALUE;
            sacc[j][3] = mvb * sacc[j][3] + (1.f - mvb) * MASK_VALUE;
            rmax0 = fmaxf(rmax0, fmaxf(sacc[j][0], sacc[j][1]));
            rmax1 = fmaxf(rmax1, fmaxf(sacc[j][2], sacc[j][3]));
        }
#pragma unroll
        for (int off = 1; off <= 2; off <<= 1) {
            rmax0 = fmaxf(rmax0, __shfl_xor_sync(0xffffffffu, rmax0, off));
            rmax1 = fmaxf(rmax1, __shfl_xor_sync(0xffffffffu, rmax1, off));
        }
        const float mn0 = fmaxf(m0, rmax0), mn1 = fmaxf(m1, rmax1);
        const float a0 = __expf(m0 - mn0), a1 = __expf(m1 - mn1);
        float ps0 = 0.f, ps1 = 0.f;
#pragma unroll
        for (int j = 0; j < 8; j++) {
            sacc[j][0] = __expf(sacc[j][0] - mn0);
            sacc[j][1] = __expf(sacc[j][1] - mn0);
            sacc[j][2] = __expf(sacc[j][2] - mn1);
            sacc[j][3] = __expf(sacc[j][3] - mn1);
            ps0 += sacc[j][0] + sacc[j][1];
            ps1 += sacc[j][2] + sacc[j][3];
        }
#pragma unroll
        for (int off = 1; off <= 2; off <<= 1) {
            ps0 += __shfl_xor_sync(0xffffffffu, ps0, off);
            ps1 += __shfl_xor_sync(0xffffffffu, ps1, off);
        }
        l0 = l0 * a0 + ps0; m0 = mn0;
        l1 = l1 * a1 + ps1; m1 = mn1;
#pragma unroll
        for (int n = 0; n < 16; n++) {
            oacc[n][0] *= a0; oacc[n][1] *= a0;
            oacc[n][2] *= a1; oacc[n][3] *= a1;
        }

        // ---- O += P V (P frags straight from sacc registers) ----
#pragma unroll
        for (int kk = 0; kk < 4; kk++) {
            const int j0 = 2 * kk, j1 = 2 * kk + 1;
            uint32_t pah[4], pal[4];
            split2(sacc[j0][0], sacc[j0][1], pah[0], pal[0]);
            split2(sacc[j0][2], sacc[j0][3], pah[1], pal[1]);
            split2(sacc[j1][0], sacc[j1][1], pah[2], pal[2]);
            split2(sacc[j1][2], sacc[j1][3], pah[3], pal[3]);
#pragma unroll
            for (int n = 0; n < 16; n++) {
                const int base = (n * 8 + g) * 36 + kk * 8 + t;
                uint32_t bh[2], bl[2];
                bh[0] = Vh[base]; bh[1] = Vh[base + 4];
                bl[0] = Vl[base]; bl[1] = Vl[base + 4];
                mma16816(oacc[n], pah, bh);
                mma16816(oacc[n], pah, bl);
                mma16816(oacc[n], pal, bh);
            }
        }
    }

    // ---- epilogue ----
    const float i0 = (l0 > 0.f) ? (1.f / l0) : 0.f;
    const float i1 = (l1 > 0.f) ? (1.f / l1) : 0.f;
    float2* o2a = (float2*)(Outg + ((size_t)b * SEQ + q0 + rg) * DIM);
    float2* o2b = (float2*)(Outg + ((size_t)b * SEQ + q0 + rg + 8) * DIM);
#pragma unroll
    for (int n = 0; n < 16; n++) {
        o2a[n * 4 + t] = make_float2(oacc[n][0] * i0, oacc[n][1] * i0);
        o2b[n * 4 + t] = make_float2(oacc[n][2] * i1, oacc[n][3] * i1);
    }
}

// ---------------------------------------------------------------------------
extern "C" void kernel_launch(void* const* d_in, const int* in_sizes, int n_in,
                              void* d_out, int out_size) {
    (void)in_sizes; (void)n_in; (void)out_size;
    const float* query = (const float*)d_in[0];
    const float* key   = (const float*)d_in[1];
    const float* value = (const float*)d_in[2];
    const float* mask  = (const float*)d_in[3];
    const float* Wq    = (const float*)d_in[4];
    const float* Wk    = (const float*)d_in[5];
    float* out = (float*)d_out;

    cudaFuncSetAttribute(attn_hmma, cudaFuncAttributeMaxDynamicSharedMemorySize, SM_TOTAL);

    proj_kernel<<<dim3(BATCH * SEQ / 128, 2), 256>>>(query, key, Wq, Wk);
    splitk_kernel<<<BATCH * SEQ * 64 / 256, 256>>>();
    vprep_kernel<<<dim3(SEQ / 64, BATCH), 256>>>(value);
    attn_hmma<<<dim3(SEQ / 128, BATCH), 256, SM_TOTAL>>>(value, mask, out);
}

// round 6
// speedup vs baseline: 3.7065x; 1.0513x over previous
#include <cuda_runtime.h>
#include <cuda_bf16.h>
#include <math.h>
#include <stdint.h>

#define BATCH 8
#define SEQ   2048
#define DIM   128
#define HDIM  128
#define MASK_VALUE -1e30f

// fp32 scratch for projected q
__device__ float g_q[BATCH * SEQ * HDIM];
// bf16-split K (row-major [b*SEQ][128] packed bf16x2 words; 16 uint4 per row)
__device__ uint4 g_khi4[BATCH * SEQ * 16];
__device__ uint4 g_klo4[BATCH * SEQ * 16];
// bf16-split transposed V: VT[b][d][kv] packed pairs along kv (256 uint4 per (b,d))
__device__ uint4 g_vthi4[BATCH * 128 * 256];
__device__ uint4 g_vtlo4[BATCH * 128 * 256];

// ---------------- helpers ----------------
__device__ __forceinline__ void split2(float x, float y, uint32_t& hi, uint32_t& lo) {
    __nv_bfloat16 hx = __float2bfloat16(x), hy = __float2bfloat16(y);
    __nv_bfloat16 lx = __float2bfloat16(x - __bfloat162float(hx));
    __nv_bfloat16 ly = __float2bfloat16(y - __bfloat162float(hy));
    hi = ((uint32_t)__bfloat16_as_ushort(hy) << 16) | (uint32_t)__bfloat16_as_ushort(hx);
    lo = ((uint32_t)__bfloat16_as_ushort(ly) << 16) | (uint32_t)__bfloat16_as_ushort(lx);
}

__device__ __forceinline__ void mma16816(float* d, const uint32_t* a, const uint32_t* b) {
    asm volatile(
        "mma.sync.aligned.m16n8k16.row.col.f32.bf16.bf16.f32 "
        "{%0,%1,%2,%3}, {%4,%5,%6,%7}, {%8,%9}, {%0,%1,%2,%3};"
        : "+f"(d[0]), "+f"(d[1]), "+f"(d[2]), "+f"(d[3])
        : "r"(a[0]), "r"(a[1]), "r"(a[2]), "r"(a[3]), "r"(b[0]), "r"(b[1]));
}

__device__ __forceinline__ uint32_t smem_u32(const void* p) {
    uint32_t a;
    asm("{ .reg .u64 t; cvta.to.shared.u64 t, %1; cvt.u32.u64 %0, t; }" : "=r"(a) : "l"(p));
    return a;
}
__device__ __forceinline__ void cp16(uint32_t dst, const void* src) {
    asm volatile("cp.async.cg.shared.global [%0], [%1], 16;"
                 :: "r"(dst), "l"(__cvta_generic_to_global(src)) : "memory");
}
#define CP_COMMIT() asm volatile("cp.async.commit_group;" ::: "memory")
#define CP_WAIT1()  asm volatile("cp.async.wait_group 1;" ::: "memory")

// ---------------- projection GEMM; K branch writes split bf16 directly -------
__global__ __launch_bounds__(256) void proj_kernel(const float* __restrict__ Xq,
                                                   const float* __restrict__ Xk,
                                                   const float* __restrict__ Wq,
                                                   const float* __restrict__ Wk) {
    __shared__ float As[8][128];
    __shared__ float Bs[8][128];
    const int tid = threadIdx.x, tx = tid & 15, ty = tid >> 4;
    const int m0 = blockIdx.x * 128;
    const int isK = (blockIdx.y != 0);
    const float* __restrict__ X = isK ? Xk : Xq;
    const float* __restrict__ W = isK ? Wk : Wq;
    float acc[8][8];
#pragma unroll
    for (int i = 0; i < 8; i++)
#pragma unroll
        for (int j = 0; j < 8; j++) acc[i][j] = 0.f;
    for (int k0 = 0; k0 < DIM; k0 += 8) {
        {
            const int row = tid >> 1, u = (tid & 1) * 4;
            float4 x = *(const float4*)&X[(size_t)(m0 + row) * DIM + k0 + u];
            As[u][row] = x.x; As[u + 1][row] = x.y; As[u + 2][row] = x.z; As[u + 3][row] = x.w;
        }
        {
            const int kk = tid >> 5, n0 = (tid & 31) * 4;
            *(float4*)&Bs[kk][n0] = *(const float4*)&W[(size_t)(k0 + kk) * HDIM + n0];
        }
        __syncthreads();
#pragma unroll
        for (int k = 0; k < 8; k++) {
            float ra[8], rb[8];
            *(float4*)&ra[0] = *(float4*)&As[k][ty * 8];
            *(float4*)&ra[4] = *(float4*)&As[k][ty * 8 + 4];
            *(float4*)&rb[0] = *(float4*)&Bs[k][tx * 8];
            *(float4*)&rb[4] = *(float4*)&Bs[k][tx * 8 + 4];
#pragma unroll
            for (int rr = 0; rr < 8; rr++)
#pragma unroll
                for (int nn = 0; nn < 8; nn++) acc[rr][nn] = fmaf(ra[rr], rb[nn], acc[rr][nn]);
        }
        __syncthreads();
    }
    if (!isK) {
#pragma unroll
        for (int rr = 0; rr < 8; rr++) {
            float* o = &g_q[(size_t)(m0 + ty * 8 + rr) * HDIM + tx * 8];
            *(float4*)&o[0] = *(float4*)&acc[rr][0];
            *(float4*)&o[4] = *(float4*)&acc[rr][4];
        }
    } else {
#pragma unroll
        for (int rr = 0; rr < 8; rr++) {
            uint4 h, l;
            split2(acc[rr][0], acc[rr][1], h.x, l.x);
            split2(acc[rr][2], acc[rr][3], h.y, l.y);
            split2(acc[rr][4], acc[rr][5], h.z, l.z);
            split2(acc[rr][6], acc[rr][7], h.w, l.w);
            const int dst = (m0 + ty * 8 + rr) * 16 + tx;  // uint4 index (16/row) FIXED
            g_khi4[dst] = h;
            g_klo4[dst] = l;
        }
    }
}

// ---------------- V: transpose + split -> g_vthi/g_vtlo ----------------
__global__ __launch_bounds__(256) void vprep_kernel(const float* __restrict__ Vg) {
    __shared__ float stg[64 * 132];
    const int tid = threadIdx.x;
    const int kv0 = blockIdx.x * 64;
    const int b   = blockIdx.y;
#pragma unroll
    for (int it = 0; it < 8; it++) {
        const int u = tid + it * 256;
        const int row = u >> 5, c4 = (u & 31) * 4;
        *(float4*)&stg[row * 132 + c4] =
            *(const float4*)&Vg[(size_t)(b * SEQ + kv0 + row) * DIM + c4];
    }
    __syncthreads();
    const int d = tid & 127, half = tid >> 7;
    uint32_t* oh = (uint32_t*)g_vthi4;
    uint32_t* ol = (uint32_t*)g_vtlo4;
#pragma unroll
    for (int i = 0; i < 16; i++) {
        const int kvw = half * 16 + i;
        uint32_t h, l;
        split2(stg[(2 * kvw) * 132 + d], stg[(2 * kvw + 1) * 132 + d], h, l);
        const int dst = (b * 128 + d) * 1024 + (kv0 >> 1) + kvw;
        oh[dst] = h;
        ol[dst] = l;
    }
}

// ---------------- fused flash attention, double-buffered cp.async ----------
// word strides: Q 68, K 68, VT 36 -> conflict-free fragment LDS
#define SQH   0
#define SQL   34816
#define SBUF  69632
#define BUFSZ 71680
#define OKH   0
#define OKL   17408
#define OVH   34816
#define OVL   53248
#define SMSK  212992      // + cur*256
#define SM_TOTAL 213504

extern __shared__ __align__(16) char smx[];

__device__ __forceinline__ void prefetch_tile(uint32_t bufb, uint32_t mskb,
                                              const float* mb, int b, int it,
                                              int tid) {
    const int kv0 = it * 64;
#pragma unroll
    for (int u4 = 0; u4 < 4; u4++) {
        const int u = tid + u4 * 256;          // 1024 uint4 per half
        const int row = u >> 4, c = u & 15;
        const int src = ((b * SEQ + kv0 + row) << 4) + c;
        cp16(bufb + OKH + row * 272 + c * 16, &g_khi4[src]);
        cp16(bufb + OKL + row * 272 + c * 16, &g_klo4[src]);
    }
#pragma unroll
    for (int u4 = 0; u4 < 4; u4++) {
        const int u = tid + u4 * 256;          // 1024 uint4 per half
        const int row = u >> 3, c = u & 7;
        const int src = (b * 128 + row) * 256 + it * 8 + c;
        cp16(bufb + OVH + row * 144 + c * 16, &g_vthi4[src]);
        cp16(bufb + OVL + row * 144 + c * 16, &g_vtlo4[src]);
    }
    if (tid < 16) cp16(mskb + tid * 16, mb + kv0 + tid * 4);
}

__global__ void __launch_bounds__(256, 1)
attn_hmma(const float* __restrict__ maskg, float* __restrict__ Outg) {
    const int tid = threadIdx.x, lane = tid & 31, w = tid >> 5;
    const int g = lane >> 2, t = lane & 3;
    const int b = blockIdx.y, q0 = blockIdx.x * 128;
    const uint32_t sb = smem_u32(smx);

    uint32_t* Qh = (uint32_t*)(smx + SQH);
    uint32_t* Ql = (uint32_t*)(smx + SQL);
    const float* mb = maskg + (size_t)b * SEQ;

    // kick off first K/V prefetch before Q staging (independent)
    prefetch_tile(sb + SBUF, sb + SMSK, mb, b, 0, tid);
    CP_COMMIT();

    // ---- load + split Q tile (128 x 128) ----
    const float2* q2 = (const float2*)(g_q + ((size_t)b * SEQ + q0) * HDIM);
#pragma unroll
    for (int it = 0; it < 32; it++) {
        const int i = tid + it * 256;
        const int row = i >> 6, wd = i & 63;
        const float2 v = q2[row * 64 + wd];
        uint32_t h, l;
        split2(v.x, v.y, h, l);
        Qh[row * 68 + wd] = h;
        Ql[row * 68 + wd] = l;
    }

    const int rg = w * 16 + g;
    const uint32_t* qhp = Qh + rg * 68;
    const uint32_t* qlp = Ql + rg * 68;

    float oacc[16][4];
#pragma unroll
    for (int n = 0; n < 16; n++)
#pragma unroll
        for (int i = 0; i < 4; i++) oacc[n][i] = 0.f;
    float m0 = -INFINITY, m1 = -INFINITY, l0 = 0.f, l1 = 0.f;

    for (int it = 0; it < SEQ / 64; it++) {
        const int cur = it & 1;
        __syncthreads();   // (A) everyone done reading buf[cur^1]
        if (it + 1 < SEQ / 64)
            prefetch_tile(sb + SBUF + (cur ^ 1) * BUFSZ,
                          sb + SMSK + (cur ^ 1) * 256, mb, b, it + 1, tid);
        CP_COMMIT();
        CP_WAIT1();        // buf[cur] (committed one group earlier) landed
        __syncthreads();   // (B) all threads' copies visible

        const char* bufp = smx + SBUF + cur * BUFSZ;
        const uint32_t* Kh = (const uint32_t*)(bufp + OKH);
        const uint32_t* Kl = (const uint32_t*)(bufp + OKL);
        const uint32_t* Vh = (const uint32_t*)(bufp + OVH);
        const uint32_t* Vl = (const uint32_t*)(bufp + OVL);
        const float*    ms = (const float*)(smx + SMSK + cur * 256);

        // ---- S = Q K^T (16 x 64 per warp), 3-product bf16 emulation ----
        float sacc[8][4];
#pragma unroll
        for (int j = 0; j < 8; j++)
#pragma unroll
            for (int i = 0; i < 4; i++) sacc[j][i] = 0.f;

#pragma unroll
        for (int k = 0; k < 8; k++) {
            const int k8 = k * 8;
            uint32_t ah[4], al[4];
            ah[0] = qhp[k8 + t];        ah[1] = qhp[544 + k8 + t];
            ah[2] = qhp[k8 + 4 + t];    ah[3] = qhp[544 + k8 + 4 + t];
            al[0] = qlp[k8 + t];        al[1] = qlp[544 + k8 + t];
            al[2] = qlp[k8 + 4 + t];    al[3] = qlp[544 + k8 + 4 + t];
#pragma unroll
            for (int j = 0; j < 8; j++) {
                const int base = (j * 8 + g) * 68 + k8 + t;
                uint32_t bh[2], bl[2];
                bh[0] = Kh[base]; bh[1] = Kh[base + 4];
                bl[0] = Kl[base]; bl[1] = Kl[base + 4];
                mma16816(sacc[j], ah, bh);
                mma16816(sacc[j], ah, bl);
                mma16816(sacc[j], al, bh);
            }
        }

        // ---- mask + online softmax ----
        float rmax0 = -INFINITY, rmax1 = -INFINITY;
#pragma unroll
        for (int j = 0; j < 8; j++) {
            const float mva = ms[j * 8 + t * 2], mvb = ms[j * 8 + t * 2 + 1];
            sacc[j][0] = mva * sacc[j][0] + (1.f - mva) * MASK_VALUE;
            sacc[j][1] = mvb * sacc[j][1] + (1.f - mvb) * MASK_VALUE;
            sacc[j][2] = mva * sacc[j][2] + (1.f - mva) * MASK_VALUE;
            sacc[j][3] = mvb * sacc[j][3] + (1.f - mvb) * MASK_VALUE;
            rmax0 = fmaxf(rmax0, fmaxf(sacc[j][0], sacc[j][1]));
            rmax1 = fmaxf(rmax1, fmaxf(sacc[j][2], sacc[j][3]));
        }
#pragma unroll
        for (int off = 1; off <= 2; off <<= 1) {
            rmax0 = fmaxf(rmax0, __shfl_xor_sync(0xffffffffu, rmax0, off));
            rmax1 = fmaxf(rmax1, __shfl_xor_sync(0xffffffffu, rmax1, off));
        }
        const float mn0 = fmaxf(m0, rmax0), mn1 = fmaxf(m1, rmax1);
        const float a0 = __expf(m0 - mn0), a1 = __expf(m1 - mn1);
        float ps0 = 0.f, ps1 = 0.f;
#pragma unroll
        for (int j = 0; j < 8; j++) {
            sacc[j][0] = __expf(sacc[j][0] - mn0);
            sacc[j][1] = __expf(sacc[j][1] - mn0);
            sacc[j][2] = __expf(sacc[j][2] - mn1);
            sacc[j][3] = __expf(sacc[j][3] - mn1);
            ps0 += sacc[j][0] + sacc[j][1];
            ps1 += sacc[j][2] + sacc[j][3];
        }
#pragma unroll
        for (int off = 1; off <= 2; off <<= 1) {
            ps0 += __shfl_xor_sync(0xffffffffu, ps0, off);
            ps1 += __shfl_xor_sync(0xffffffffu, ps1, off);
        }
        l0 = l0 * a0 + ps0; m0 = mn0;
        l1 = l1 * a1 + ps1; m1 = mn1;
#pragma unroll
        for (int n = 0; n < 16; n++) {
            oacc[n][0] *= a0; oacc[n][1] *= a0;
            oacc[n][2] *= a1; oacc[n][3] *= a1;
        }

        // ---- O += P V (P frags straight from sacc registers) ----
#pragma unroll
        for (int kk = 0; kk < 4; kk++) {
            const int j0 = 2 * kk, j1 = 2 * kk + 1;
            uint32_t pah[4], pal[4];
            split2(sacc[j0][0], sacc[j0][1], pah[0], pal[0]);
            split2(sacc[j0][2], sacc[j0][3], pah[1], pal[1]);
            split2(sacc[j1][0], sacc[j1][1], pah[2], pal[2]);
            split2(sacc[j1][2], sacc[j1][3], pah[3], pal[3]);
#pragma unroll
            for (int n = 0; n < 16; n++) {
                const int base = (n * 8 + g) * 36 + kk * 8 + t;
                uint32_t bh[2], bl[2];
                bh[0] = Vh[base]; bh[1] = Vh[base + 4];
                bl[0] = Vl[base]; bl[1] = Vl[base + 4];
                mma16816(oacc[n], pah, bh);
                mma16816(oacc[n], pah, bl);
                mma16816(oacc[n], pal, bh);
            }
        }
    }

    // ---- epilogue ----
    const float i0 = (l0 > 0.f) ? (1.f / l0) : 0.f;
    const float i1 = (l1 > 0.f) ? (1.f / l1) : 0.f;
    float2* o2a = (float2*)(Outg + ((size_t)b * SEQ + q0 + rg) * DIM);
    float2* o2b = (float2*)(Outg + ((size_t)b * SEQ + q0 + rg + 8) * DIM);
#pragma unroll
    for (int n = 0; n < 16; n++) {
        o2a[n * 4 + t] = make_float2(oacc[n][0] * i0, oacc[n][1] * i0);
        o2b[n * 4 + t] = make_float2(oacc[n][2] * i1, oacc[n][3] * i1);
    }
}

// ---------------------------------------------------------------------------
extern "C" void kernel_launch(void* const* d_in, const int* in_sizes, int n_in,
                              void* d_out, int out_size) {
    (void)in_sizes; (void)n_in; (void)out_size;
    const float* query = (const float*)d_in[0];
    const float* key   = (const float*)d_in[1];
    const float* value = (const float*)d_in[2];
    const float* mask  = (const float*)d_in[3];
    const float* Wq    = (const float*)d_in[4];
    const float* Wk    = (const float*)d_in[5];
    float* out = (float*)d_out;

    cudaFuncSetAttribute(attn_hmma, cudaFuncAttributeMaxDynamicSharedMemorySize, SM_TOTAL);

    proj_kernel<<<dim3(BATCH * SEQ / 128, 2), 256>>>(query, key, Wq, Wk);
    vprep_kernel<<<dim3(SEQ / 64, BATCH), 256>>>(value);
    attn_hmma<<<dim3(SEQ / 128, BATCH), 256, SM_TOTAL>>>(mask, out);
}